// round 9
// baseline (speedup 1.0000x reference)
#include <cuda_runtime.h>
#include <cuda_fp16.h>
#include <cstdint>

// ConvDemodulated: out[b,o,hw] = clip( sum_i x[b,i,hw] * Wn[o,i] + bias[o], -256, 256 )
// R6: fp16 m16n8k16 GEMM, 2 tiles per CTA software pipeline:
// tile1 staging (LDG+pack+STS) interleaved into tile0's mma loop so DRAM stays
// busy through the compute phase. Streaming cache hints on x/out.

#define CIN   64
#define COUT  64
#define HWSZ  65536
#define S2U   132      // staging stride (uint2), mod 16 == 4 -> conflict-free LDS.64
#define SEF   136      // epilogue stride (floats)

#define SMEM_STAGE_B (16 * S2U * 8)            // 16896 B per staging buffer
#define SMEM_EPI_B   (32 * SEF * 4)            // 17408 B epilogue half-buffer
#define SMEM_TOTAL   (2 * SMEM_STAGE_B + SMEM_EPI_B)   // 51200 B

// Pre-packed fp16 A-fragments: [kb(4)][mt(4)][lane(32)] uint4 (8 halves each).
__device__ uint4 g_wfrag16[4 * 4 * 32];

__device__ __forceinline__ uint32_t pack_h2(float lo, float hi) {
    __half2 h = __floats2half2_rn(lo, hi);
    return *reinterpret_cast<uint32_t*>(&h);
}

// ---------------- weight prep ----------------
__global__ void prep_w_kernel(const float* __restrict__ w) {
    __shared__ float wn[COUT * CIN];
    const int tt = threadIdx.x;   // 128 threads
    if (tt < COUT) {
        float s = 1e-8f;
#pragma unroll
        for (int k = 0; k < CIN; k++) {
            float v = w[tt * CIN + k];
            s += v * v;
        }
        const float d = rsqrtf(s);
#pragma unroll
        for (int k = 0; k < CIN; k++)
            wn[tt * CIN + k] = w[tt * CIN + k] * d;
    }
    __syncthreads();
    // A-frag (m16n8k16 row-major): r = mt*16 + lane/4, c = kb*16 + 2*(lane%4)
    for (int e = tt; e < 512; e += 128) {
        int lane = e & 31, mt = (e >> 5) & 3, kb = e >> 7;
        int r = mt * 16 + (lane >> 2);
        int c = kb * 16 + 2 * (lane & 3);
        uint4 v;
        v.x = pack_h2(wn[r * CIN + c],           wn[r * CIN + c + 1]);
        v.y = pack_h2(wn[(r + 8) * CIN + c],     wn[(r + 8) * CIN + c + 1]);
        v.z = pack_h2(wn[r * CIN + c + 8],       wn[r * CIN + c + 9]);
        v.w = pack_h2(wn[(r + 8) * CIN + c + 8], wn[(r + 8) * CIN + c + 9]);
        g_wfrag16[(kb * 4 + mt) * 32 + lane] = v;
    }
}

// ---------------- main kernel ----------------
__global__ void __launch_bounds__(128, 4)
conv_mma_kernel(const float* __restrict__ x, const float* __restrict__ bias,
                float* __restrict__ out) {
    extern __shared__ __align__(16) char dsm[];
    uint2* SA  = (uint2*)dsm;                                // tile0 staging
    uint2* SBf = (uint2*)(dsm + SMEM_STAGE_B);               // tile1 staging
    float* SEh = (float*)(dsm + 2 * SMEM_STAGE_B);           // epi half-buffer

    const int tid  = threadIdx.x;
    const int lane = tid & 31;
    const int wid  = tid >> 5;     // 0..3
    const int cw   = wid & 1;      // cout half
    const int ph   = wid >> 1;     // pixel half
    const int t    = lane & 3;
    const int g    = lane >> 2;
    const int pixb = ph * 64;

    const int pixglob = blockIdx.x * 256;          // 2 tiles of 128 pixels
    const int b   = pixglob >> 16;
    const int hw0 = pixglob & (HWSZ - 1);
    const float* xb0 = x + ((size_t)b << 22) + hw0;
    const float* xb1 = xb0 + 128;
    float* ob0 = out + ((size_t)b << 22) + hw0;
    float* ob1 = ob0 + 128;

    // bias values for this thread's rows
    float bv[2][2];
#pragma unroll
    for (int m = 0; m < 2; m++) {
        bv[m][0] = __ldg(bias + cw * 32 + m * 16 + g);
        bv[m][1] = __ldg(bias + cw * 32 + m * 16 + g + 8);
    }

    // ---- stage tile0 -> SA ----
#pragma unroll
    for (int it = 0; it < 4; it++) {
        const int q  = it * 4 + wid;
        const int k0 = it * 16 + wid * 2;
        const float* rp = xb0 + ((size_t)k0 << 16) + lane * 4;
        float4 va = __ldcs((const float4*)rp);
        float4 vb = __ldcs((const float4*)(rp + (1 << 16)));
        float4 vc = __ldcs((const float4*)(rp + (8 << 16)));
        float4 vd = __ldcs((const float4*)(rp + (9 << 16)));
        uint4 o0, o1;
        o0.x = pack_h2(va.x, vb.x); o0.y = pack_h2(vc.x, vd.x);
        o0.z = pack_h2(va.y, vb.y); o0.w = pack_h2(vc.y, vd.y);
        o1.x = pack_h2(va.z, vb.z); o1.y = pack_h2(vc.z, vd.z);
        o1.z = pack_h2(va.w, vb.w); o1.w = pack_h2(vc.w, vd.w);
        *(uint4*)&SA[q * S2U + lane * 4]     = o0;
        *(uint4*)&SA[q * S2U + lane * 4 + 2] = o1;
    }
    __syncthreads();

    float acc[2][8][4];
#pragma unroll
    for (int m = 0; m < 2; m++)
#pragma unroll
        for (int nt = 0; nt < 8; nt++)
#pragma unroll
            for (int j = 0; j < 4; j++) acc[m][nt][j] = 0.0f;

    // ---- mma tile0, interleaved with tile1 staging (LDG + pack + STS -> SBf) ----
    // unroll 1: keeps transient load regs per-iteration, prevents front-batching.
#pragma unroll 1
    for (int kb = 0; kb < 4; kb++) {
        // prefetch tile1 chunk: q-row kb*4 + wid
        const int k0 = kb * 16 + wid * 2;
        const float* rp = xb1 + ((size_t)k0 << 16) + lane * 4;
        float4 va = __ldcs((const float4*)rp);
        float4 vb = __ldcs((const float4*)(rp + (1 << 16)));
        float4 vc = __ldcs((const float4*)(rp + (8 << 16)));
        float4 vd = __ldcs((const float4*)(rp + (9 << 16)));

        uint4 aw0 = __ldg(&g_wfrag16[(kb * 4 + cw * 2) * 32 + lane]);
        uint4 aw1 = __ldg(&g_wfrag16[(kb * 4 + cw * 2 + 1) * 32 + lane]);

#pragma unroll
        for (int nt = 0; nt < 8; nt++) {
            const uint2 bb = SA[(kb * 4 + t) * S2U + pixb + nt * 8 + g];
            asm volatile(
                "mma.sync.aligned.m16n8k16.row.col.f32.f16.f16.f32 "
                "{%0,%1,%2,%3}, {%4,%5,%6,%7}, {%8,%9}, {%0,%1,%2,%3};"
                : "+f"(acc[0][nt][0]), "+f"(acc[0][nt][1]),
                  "+f"(acc[0][nt][2]), "+f"(acc[0][nt][3])
                : "r"(aw0.x), "r"(aw0.y), "r"(aw0.z), "r"(aw0.w),
                  "r"(bb.x), "r"(bb.y));
            asm volatile(
                "mma.sync.aligned.m16n8k16.row.col.f32.f16.f16.f32 "
                "{%0,%1,%2,%3}, {%4,%5,%6,%7}, {%8,%9}, {%0,%1,%2,%3};"
                : "+f"(acc[1][nt][0]), "+f"(acc[1][nt][1]),
                  "+f"(acc[1][nt][2]), "+f"(acc[1][nt][3])
                : "r"(aw1.x), "r"(aw1.y), "r"(aw1.z), "r"(aw1.w),
                  "r"(bb.x), "r"(bb.y));
        }

        // pack + store tile1 chunk (no sync needed: SBf unread until barrier below)
        uint4 o0, o1;
        o0.x = pack_h2(va.x, vb.x); o0.y = pack_h2(vc.x, vd.x);
        o0.z = pack_h2(va.y, vb.y); o0.w = pack_h2(vc.y, vd.y);
        o1.x = pack_h2(va.z, vb.z); o1.y = pack_h2(vc.z, vd.z);
        o1.z = pack_h2(va.w, vb.w); o1.w = pack_h2(vc.w, vd.w);
        const int q = kb * 4 + wid;
        *(uint4*)&SBf[q * S2U + lane * 4]     = o0;
        *(uint4*)&SBf[q * S2U + lane * 4 + 2] = o1;
    }
    __syncthreads();   // SBf visible; SA reads done

    // ---- epilogue (bias+clamp -> smem transpose in 2 row-halves -> coalesced STG) ----
    auto epilogue = [&](float* ob) {
#pragma unroll
        for (int m = 0; m < 2; m++) {
            const int rl = cw * 16 + g;    // row_local within half m
#pragma unroll
            for (int nt = 0; nt < 8; nt++) {
                const int col = pixb + nt * 8 + t * 2;
                float2 v0, v1;
                v0.x = fminf(fmaxf(acc[m][nt][0] + bv[m][0], -256.0f), 256.0f);
                v0.y = fminf(fmaxf(acc[m][nt][1] + bv[m][0], -256.0f), 256.0f);
                v1.x = fminf(fmaxf(acc[m][nt][2] + bv[m][1], -256.0f), 256.0f);
                v1.y = fminf(fmaxf(acc[m][nt][3] + bv[m][1], -256.0f), 256.0f);
                *(float2*)&SEh[rl * SEF + col]       = v0;
                *(float2*)&SEh[(rl + 8) * SEF + col] = v1;
            }
            __syncthreads();
#pragma unroll
            for (int p = 0; p < 8; p++) {
                const int r = p * 4 + wid;                      // row_local
                const int grow = (r >> 4) * 32 + m * 16 + (r & 15);
                float4 v = *(const float4*)&SEh[r * SEF + lane * 4];
                __stcs((float4*)(ob + ((size_t)grow << 16) + lane * 4), v);
            }
            __syncthreads();
        }
    };

    epilogue(ob0);

    // ---- mma tile1 (reads SBf; no gmem loads besides L1-hot aw) ----
#pragma unroll
    for (int m = 0; m < 2; m++)
#pragma unroll
        for (int nt = 0; nt < 8; nt++)
#pragma unroll
            for (int j = 0; j < 4; j++) acc[m][nt][j] = 0.0f;

#pragma unroll
    for (int kb = 0; kb < 4; kb++) {
        uint4 aw0 = __ldg(&g_wfrag16[(kb * 4 + cw * 2) * 32 + lane]);
        uint4 aw1 = __ldg(&g_wfrag16[(kb * 4 + cw * 2 + 1) * 32 + lane]);
#pragma unroll
        for (int nt = 0; nt < 8; nt++) {
            const uint2 bb = SBf[(kb * 4 + t) * S2U + pixb + nt * 8 + g];
            asm volatile(
                "mma.sync.aligned.m16n8k16.row.col.f32.f16.f16.f32 "
                "{%0,%1,%2,%3}, {%4,%5,%6,%7}, {%8,%9}, {%0,%1,%2,%3};"
                : "+f"(acc[0][nt][0]), "+f"(acc[0][nt][1]),
                  "+f"(acc[0][nt][2]), "+f"(acc[0][nt][3])
                : "r"(aw0.x), "r"(aw0.y), "r"(aw0.z), "r"(aw0.w),
                  "r"(bb.x), "r"(bb.y));
            asm volatile(
                "mma.sync.aligned.m16n8k16.row.col.f32.f16.f16.f32 "
                "{%0,%1,%2,%3}, {%4,%5,%6,%7}, {%8,%9}, {%0,%1,%2,%3};"
                : "+f"(acc[1][nt][0]), "+f"(acc[1][nt][1]),
                  "+f"(acc[1][nt][2]), "+f"(acc[1][nt][3])
                : "r"(aw1.x), "r"(aw1.y), "r"(aw1.z), "r"(aw1.w),
                  "r"(bb.x), "r"(bb.y));
        }
    }

    epilogue(ob1);
}

// ---------------- launch ----------------
extern "C" void kernel_launch(void* const* d_in, const int* in_sizes, int n_in,
                              void* d_out, int out_size) {
    const float* x    = (const float*)d_in[0];
    const float* w    = (const float*)d_in[1];
    const float* bias = (const float*)d_in[2];
    float* out = (float*)d_out;

    static bool attr_set = false;
    if (!attr_set) {
        cudaFuncSetAttribute(conv_mma_kernel,
                             cudaFuncAttributeMaxDynamicSharedMemorySize, SMEM_TOTAL);
        attr_set = true;
    }

    prep_w_kernel<<<1, 128>>>(w);

    const int total_pix = 16 * HWSZ;
    const int nblocks = total_pix / 256;     // 4096
    conv_mma_kernel<<<nblocks, 128, SMEM_TOTAL>>>(x, bias, out);
}

// round 10
// speedup vs baseline: 1.1273x; 1.1273x over previous
#include <cuda_runtime.h>
#include <cuda_fp16.h>
#include <cstdint>

// ConvDemodulated: out[b,o,hw] = clip( sum_i x[b,i,hw] * Wn[o,i] + bias[o], -256, 256 )
// R7 = R4 (best: 88.6us) + occupancy push: launch_bounds(128,5), per-kb
// software-pipelined W-fragment loads (frees 24 regs), staging unroll 2.
// Rationale: cross-CTA phase overlap is what saturates DRAM; more CTAs/SM > 
// explicit intra-CTA pipelining (R6 regression).

#define CIN   64
#define COUT  64
#define HWSZ  65536
#define PTILE 128      // pixels per CTA
#define S2U   132      // staging stride (uint2), mod 16 == 4 -> conflict-free LDS.64
#define SEF   136      // epilogue stride (floats)

// Pre-packed fp16 A-fragments: [kb(4)][mt(4)][lane(32)] uint4 (8 halves each).
__device__ uint4 g_wfrag16[4 * 4 * 32];

__device__ __forceinline__ uint32_t pack_h2(float lo, float hi) {
    __half2 h = __floats2half2_rn(lo, hi);
    return *reinterpret_cast<uint32_t*>(&h);
}

// ---------------- weight prep: normalize rows, pack m16n8k16 A-frags ----------------
__global__ void prep_w_kernel(const float* __restrict__ w) {
    __shared__ float wn[COUT * CIN];
    const int tt = threadIdx.x;   // 128 threads
    if (tt < COUT) {
        float s = 1e-8f;
#pragma unroll
        for (int k = 0; k < CIN; k++) {
            float v = w[tt * CIN + k];
            s += v * v;
        }
        const float d = rsqrtf(s);
#pragma unroll
        for (int k = 0; k < CIN; k++)
            wn[tt * CIN + k] = w[tt * CIN + k] * d;
    }
    __syncthreads();
    // A-frag (m16n8k16 row-major): r = mt*16 + lane/4, c = kb*16 + 2*(lane%4)
    for (int e = tt; e < 512; e += 128) {
        int lane = e & 31, mt = (e >> 5) & 3, kb = e >> 7;
        int r = mt * 16 + (lane >> 2);
        int c = kb * 16 + 2 * (lane & 3);
        uint4 v;
        v.x = pack_h2(wn[r * CIN + c],           wn[r * CIN + c + 1]);
        v.y = pack_h2(wn[(r + 8) * CIN + c],     wn[(r + 8) * CIN + c + 1]);
        v.z = pack_h2(wn[r * CIN + c + 8],       wn[r * CIN + c + 9]);
        v.w = pack_h2(wn[(r + 8) * CIN + c + 8], wn[(r + 8) * CIN + c + 9]);
        g_wfrag16[(kb * 4 + mt) * 32 + lane] = v;
    }
}

// ---------------- main kernel ----------------
__global__ void __launch_bounds__(128, 5)
conv_mma_kernel(const float* __restrict__ x, const float* __restrict__ bias,
                float* __restrict__ out) {
    // Union: staging (16 quad-rows x 132 uint2 = 16.9KB) then epilogue (64 x 136 fp32 = 34.8KB)
    __shared__ __align__(16) float SE[COUT * SEF];
    uint2* SB = (uint2*)SE;

    const int tid  = threadIdx.x;
    const int lane = tid & 31;
    const int wid  = tid >> 5;     // 0..3
    const int cw   = wid & 1;      // cout half
    const int ph   = wid >> 1;     // pixel half
    const int t    = lane & 3;
    const int g    = lane >> 2;
    const int pixb = ph * 64;

    const int pixglob = blockIdx.x * PTILE;
    const int b   = pixglob >> 16;
    const int hw0 = pixglob & (HWSZ - 1);
    const float* xb = x + ((size_t)b << 22) + hw0;

    // ---- stage X: quad-row q holds fp16 pairs of k rows {k0,k0+1} / {k0+8,k0+9} ----
    // unroll 2: 8 LDG.128 in flight per chunk (32 transient regs) -> good MLP, fits reg budget.
#pragma unroll 2
    for (int it = 0; it < 4; it++) {
        const int q  = it * 4 + wid;                 // 0..15
        const int k0 = it * 16 + wid * 2;
        const float* rp = xb + ((size_t)k0 << 16) + lane * 4;
        float4 va = __ldcs((const float4*)rp);
        float4 vb = __ldcs((const float4*)(rp + (1 << 16)));
        float4 vc = __ldcs((const float4*)(rp + (8 << 16)));
        float4 vd = __ldcs((const float4*)(rp + (9 << 16)));
        uint4 o0, o1;
        o0.x = pack_h2(va.x, vb.x); o0.y = pack_h2(vc.x, vd.x);
        o0.z = pack_h2(va.y, vb.y); o0.w = pack_h2(vc.y, vd.y);
        o1.x = pack_h2(va.z, vb.z); o1.y = pack_h2(vc.z, vd.z);
        o1.z = pack_h2(va.w, vb.w); o1.w = pack_h2(vc.w, vd.w);
        *(uint4*)&SB[q * S2U + lane * 4]     = o0;
        *(uint4*)&SB[q * S2U + lane * 4 + 2] = o1;
    }

    float acc[2][8][4];
#pragma unroll
    for (int m = 0; m < 2; m++)
#pragma unroll
        for (int nt = 0; nt < 8; nt++)
#pragma unroll
            for (int j = 0; j < 4; j++) acc[m][nt][j] = 0.0f;

    __syncthreads();

    // ---- mainloop: 4 k-blocks x 8 n-tiles x 2 m-tiles of m16n8k16 ----
    // W A-frags software-pipelined one kb ahead (L1-hot, 16 regs live).
    uint4 aw0 = __ldg(&g_wfrag16[(cw * 2) * 32 + lane]);
    uint4 aw1 = __ldg(&g_wfrag16[(cw * 2 + 1) * 32 + lane]);

#pragma unroll
    for (int kb = 0; kb < 4; kb++) {
        uint4 nw0, nw1;
        if (kb < 3) {
            nw0 = __ldg(&g_wfrag16[((kb + 1) * 4 + cw * 2) * 32 + lane]);
            nw1 = __ldg(&g_wfrag16[((kb + 1) * 4 + cw * 2 + 1) * 32 + lane]);
        }
#pragma unroll
        for (int nt = 0; nt < 8; nt++) {
            const uint2 bb = SB[(kb * 4 + t) * S2U + pixb + nt * 8 + g];
            asm volatile(
                "mma.sync.aligned.m16n8k16.row.col.f32.f16.f16.f32 "
                "{%0,%1,%2,%3}, {%4,%5,%6,%7}, {%8,%9}, {%0,%1,%2,%3};"
                : "+f"(acc[0][nt][0]), "+f"(acc[0][nt][1]),
                  "+f"(acc[0][nt][2]), "+f"(acc[0][nt][3])
                : "r"(aw0.x), "r"(aw0.y), "r"(aw0.z), "r"(aw0.w),
                  "r"(bb.x), "r"(bb.y));
            asm volatile(
                "mma.sync.aligned.m16n8k16.row.col.f32.f16.f16.f32 "
                "{%0,%1,%2,%3}, {%4,%5,%6,%7}, {%8,%9}, {%0,%1,%2,%3};"
                : "+f"(acc[1][nt][0]), "+f"(acc[1][nt][1]),
                  "+f"(acc[1][nt][2]), "+f"(acc[1][nt][3])
                : "r"(aw1.x), "r"(aw1.y), "r"(aw1.z), "r"(aw1.w),
                  "r"(bb.x), "r"(bb.y));
        }
        if (kb < 3) { aw0 = nw0; aw1 = nw1; }
    }

    __syncthreads();   // mainloop smem reads done before union overwrite

    // ---- epilogue pt1: bias+clamp, STS into [cout][pix] ----
#pragma unroll
    for (int m = 0; m < 2; m++) {
        const int row0 = cw * 32 + m * 16 + g;
        const float bv0 = __ldg(bias + row0);
        const float bv1 = __ldg(bias + row0 + 8);
#pragma unroll
        for (int nt = 0; nt < 8; nt++) {
            const int col = pixb + nt * 8 + t * 2;
            float2 v0, v1;
            v0.x = fminf(fmaxf(acc[m][nt][0] + bv0, -256.0f), 256.0f);
            v0.y = fminf(fmaxf(acc[m][nt][1] + bv0, -256.0f), 256.0f);
            v1.x = fminf(fmaxf(acc[m][nt][2] + bv1, -256.0f), 256.0f);
            v1.y = fminf(fmaxf(acc[m][nt][3] + bv1, -256.0f), 256.0f);
            *(float2*)&SE[row0 * SEF + col]       = v0;
            *(float2*)&SE[(row0 + 8) * SEF + col] = v1;
        }
    }
    __syncthreads();

    // ---- epilogue pt2: coalesced 512B-per-warp copy out ----
    float* ob = out + ((size_t)b << 22) + hw0;
#pragma unroll
    for (int p = 0; p < 16; p++) {
        const int row = p * 4 + wid;               // cout
        float4 v = *(const float4*)&SE[row * SEF + lane * 4];
        __stcs((float4*)(ob + ((size_t)row << 16) + lane * 4), v);
    }
}

// ---------------- launch ----------------
extern "C" void kernel_launch(void* const* d_in, const int* in_sizes, int n_in,
                              void* d_out, int out_size) {
    const float* x    = (const float*)d_in[0];
    const float* w    = (const float*)d_in[1];
    const float* bias = (const float*)d_in[2];
    float* out = (float*)d_out;

    prep_w_kernel<<<1, 128>>>(w);

    const int total_pix = 16 * HWSZ;
    const int nblocks = total_pix / PTILE;   // 8192
    conv_mma_kernel<<<nblocks, 128>>>(x, bias, out);
}